// round 2
// baseline (speedup 1.0000x reference)
#include <cuda_runtime.h>
#include <stdint.h>

// Problem constants
#define BB   32
#define DD   256
#define TT   2048
#define KK   1024
#define NVEC (BB * TT)          // 65536 vectors
#define QOUT (BB * DD * TT)     // 16777216 quantized elements

// Tiling for the argmin kernel
#define BLK_V   64              // vectors per block
#define KC      128             // code chunk
#define DSL     64              // d-slice
#define WS_STR  132             // padded stride for W slice [d][k]; 16B-aligned rows

// Scratch (no allocations allowed -> device globals)
__device__ float g_s2[KK];
__device__ int   g_idx[NVEC];

// ---------------------------------------------------------------------------
// f32x2 packed helpers (Blackwell FFMA2)
// ---------------------------------------------------------------------------
__device__ __forceinline__ unsigned long long dup_f32x2(float x) {
    unsigned long long r;
    asm("mov.b64 %0, {%1, %1};" : "=l"(r) : "f"(x));
    return r;
}
__device__ __forceinline__ void fma_f32x2(unsigned long long& d,
                                          unsigned long long a,
                                          unsigned long long b) {
    asm("fma.rn.f32x2 %0, %1, %2, %0;" : "+l"(d) : "l"(a), "l"(b));
}

// ---------------------------------------------------------------------------
// Kernel 0: per-code squared norms (sequential fp32 FMA)
// ---------------------------------------------------------------------------
__global__ void vq_s2_kernel(const float* __restrict__ w) {
    int k = blockIdx.x * blockDim.x + threadIdx.x;
    if (k < KK) {
        const float* row = w + k * DD;
        float s = 0.0f;
        #pragma unroll 8
        for (int d = 0; d < DD; d++) s = fmaf(row[d], row[d], s);
        g_s2[k] = s;
    }
}

// ---------------------------------------------------------------------------
// Kernel 1: argmin over codes. 64 vectors/block, 256 threads.
// Thread tile: 4 vectors x 8 codes; accumulators as f32x2 pairs along k.
// dist = RN( RN(s1+s2) - 2*m )  (fmaf(-2, m, S): single rounding, identical
// to reference's (s1+s2) - 2m since *2 is exact). Ties -> lowest index via
// packed (dist_bits<<32)|k u64 min (dist is strictly positive here).
// ---------------------------------------------------------------------------
__global__ void __launch_bounds__(256, 2)
vq_argmin_kernel(const float* __restrict__ inputs,
                 const float* __restrict__ weight) {
    extern __shared__ float smem[];
    float* Xs  = smem;                       // [256][64]  = 16384 floats
    float* Ws  = Xs + DD * BLK_V;            // [64][132]  =  8448 floats
    float* s1s = Ws + DSL * WS_STR;          // [64]
    float* s2c = s1s + BLK_V;                // [128]
    unsigned long long* red =
        (unsigned long long*)(s2c + KC);     // [64][16] u64; offset 100096B -> 8B aligned

    const int tid  = threadIdx.x;
    const int tcol = tid & 15;               // vector group (16 groups of 4)
    const int trow = tid >> 4;               // code group   (16 groups of 8)
    const int v0   = tcol * 4;
    const int k0   = trow * 8;

    const int i0 = blockIdx.x * BLK_V;       // first vector of this block
    const int b  = i0 >> 11;                 // i0 / TT  (TT = 2048, BLK_V | TT)
    const int t0 = i0 & (TT - 1);

    // ---- load X tile: Xs[d][v] = inputs[b, d, t0+v] (coalesced along t) ----
    {
        const float* xin = inputs + (size_t)b * DD * TT + t0;
        for (int l = tid; l < DD * BLK_V; l += 256) {
            int d = l >> 6;
            int v = l & 63;
            Xs[d * BLK_V + v] = xin[d * TT + v];
        }
    }
    __syncthreads();

    // ---- s1 per vector: sequential fp32 FMA over d ----
    if (tid < BLK_V) {
        float s = 0.0f;
        #pragma unroll 8
        for (int d = 0; d < DD; d++) {
            float x = Xs[d * BLK_V + tid];
            s = fmaf(x, x, s);
        }
        s1s[tid] = s;
    }
    __syncthreads();

    float s1v[4];
    #pragma unroll
    for (int v = 0; v < 4; v++) s1v[v] = s1s[v0 + v];

    unsigned long long best[4];
    #pragma unroll
    for (int v = 0; v < 4; v++) best[v] = ~0ull;

    for (int kc = 0; kc < KK / KC; kc++) {
        // stage s2 chunk (ordered by the first __syncthreads in the ds loop)
        if (tid < KC) s2c[tid] = g_s2[kc * KC + tid];

        unsigned long long acc[4][4];
        #pragma unroll
        for (int v = 0; v < 4; v++)
            #pragma unroll
            for (int p = 0; p < 4; p++) acc[v][p] = 0ull;

        for (int ds = 0; ds < DD / DSL; ds++) {
            __syncthreads();
            // load W slice: Ws[dd][k] = weight[kc*KC + k][ds*DSL + dd]
            // gmem reads coalesced along d; smem store stride-132 (4-way conflict, cheap)
            {
                const float* wg = weight + (size_t)(kc * KC) * DD + ds * DSL;
                for (int l = tid; l < KC * DSL; l += 256) {
                    int k  = l >> 6;          // 0..127
                    int dd = l & 63;          // 0..63
                    Ws[dd * WS_STR + k] = wg[k * DD + dd];
                }
            }
            __syncthreads();

            #pragma unroll 4
            for (int dd = 0; dd < DSL; dd++) {
                // x values for our 4 vectors at this d
                float4 xv = *(const float4*)&Xs[(ds * DSL + dd) * BLK_V + v0];
                // w pairs for our 8 codes at this d (naturally paired along k)
                ulonglong2 wa = *(const ulonglong2*)&Ws[dd * WS_STR + k0];
                ulonglong2 wb = *(const ulonglong2*)&Ws[dd * WS_STR + k0 + 4];
                unsigned long long wp0 = wa.x, wp1 = wa.y, wp2 = wb.x, wp3 = wb.y;

                unsigned long long x0 = dup_f32x2(xv.x);
                unsigned long long x1 = dup_f32x2(xv.y);
                unsigned long long x2 = dup_f32x2(xv.z);
                unsigned long long x3 = dup_f32x2(xv.w);

                fma_f32x2(acc[0][0], x0, wp0); fma_f32x2(acc[0][1], x0, wp1);
                fma_f32x2(acc[0][2], x0, wp2); fma_f32x2(acc[0][3], x0, wp3);
                fma_f32x2(acc[1][0], x1, wp0); fma_f32x2(acc[1][1], x1, wp1);
                fma_f32x2(acc[1][2], x1, wp2); fma_f32x2(acc[1][3], x1, wp3);
                fma_f32x2(acc[2][0], x2, wp0); fma_f32x2(acc[2][1], x2, wp1);
                fma_f32x2(acc[2][2], x2, wp2); fma_f32x2(acc[2][3], x2, wp3);
                fma_f32x2(acc[3][0], x3, wp0); fma_f32x2(acc[3][1], x3, wp1);
                fma_f32x2(acc[3][2], x3, wp2); fma_f32x2(acc[3][3], x3, wp3);
            }
        }

        // ---- distance + running argmin for this chunk ----
        #pragma unroll
        for (int v = 0; v < 4; v++) {
            #pragma unroll
            for (int p = 0; p < 4; p++) {
                unsigned int lo = (unsigned int)(acc[v][p] & 0xFFFFFFFFull);
                unsigned int hi = (unsigned int)(acc[v][p] >> 32);
                float mlo = __uint_as_float(lo);
                float mhi = __uint_as_float(hi);
                int klo = kc * KC + k0 + p * 2;
                int khi = klo + 1;
                float Slo = s1v[v] + s2c[k0 + p * 2];
                float Shi = s1v[v] + s2c[k0 + p * 2 + 1];
                float dlo = fmaf(-2.0f, mlo, Slo);
                float dhi = fmaf(-2.0f, mhi, Shi);
                unsigned long long keylo =
                    ((unsigned long long)__float_as_uint(dlo) << 32) | (unsigned int)klo;
                unsigned long long keyhi =
                    ((unsigned long long)__float_as_uint(dhi) << 32) | (unsigned int)khi;
                if (keylo < best[v]) best[v] = keylo;
                if (keyhi < best[v]) best[v] = keyhi;
            }
        }
        __syncthreads();  // protect s2c before next chunk overwrites it
    }

    // ---- cross-thread reduction: 16 code-groups per vector ----
    #pragma unroll
    for (int v = 0; v < 4; v++) red[(v0 + v) * 16 + trow] = best[v];
    __syncthreads();
    if (tid < BLK_V) {
        unsigned long long m = red[tid * 16];
        #pragma unroll
        for (int j = 1; j < 16; j++) {
            unsigned long long c = red[tid * 16 + j];
            if (c < m) m = c;
        }
        g_idx[i0 + tid] = (int)(m & 0xFFFFFFFFull);
    }
}

// ---------------------------------------------------------------------------
// Kernel 2: gather quantized output. out[b, d, t] = weight[idx[b*TT+t], d]
// float4 stores along t; weight (1MB) stays L2-resident.
// ---------------------------------------------------------------------------
__global__ void vq_gather_kernel(const float* __restrict__ weight,
                                 float* __restrict__ out) {
    int gid = blockIdx.x * blockDim.x + threadIdx.x;
    const int T4 = TT / 4;
    if (gid >= BB * DD * T4) return;
    int t4  = gid % T4;
    int rem = gid / T4;
    int d   = rem % DD;
    int b   = rem / DD;
    int t   = t4 * 4;
    int base = b * TT + t;
    int i0 = g_idx[base + 0];
    int i1 = g_idx[base + 1];
    int i2 = g_idx[base + 2];
    int i3 = g_idx[base + 3];
    float4 o;
    o.x = weight[i0 * DD + d];
    o.y = weight[i1 * DD + d];
    o.z = weight[i2 * DD + d];
    o.w = weight[i3 * DD + d];
    *(float4*)&out[((size_t)b * DD + d) * TT + t] = o;
}

// ---------------------------------------------------------------------------
// Kernel 3: emit indices as output dtype (float32), after quantized block
// ---------------------------------------------------------------------------
__global__ void vq_idx_kernel(float* __restrict__ out) {
    int i = blockIdx.x * blockDim.x + threadIdx.x;
    if (i < NVEC) out[i] = (float)g_idx[i];
}

// ---------------------------------------------------------------------------
// Launch
// ---------------------------------------------------------------------------
extern "C" void kernel_launch(void* const* d_in, const int* in_sizes, int n_in,
                              void* d_out, int out_size) {
    const float* inputs = (const float*)d_in[0];
    const float* weight = (const float*)d_in[1];
    float* out = (float*)d_out;

    // smem: 16384 + 8448 + 64 + 128 floats + 64*16 u64 = 100096 + 8192 = 108288 B
    const int SMEM_BYTES = (DD * BLK_V + DSL * WS_STR + BLK_V + KC) * 4
                         + BLK_V * 16 * 8;
    cudaFuncSetAttribute(vq_argmin_kernel,
                         cudaFuncAttributeMaxDynamicSharedMemorySize, SMEM_BYTES);

    vq_s2_kernel<<<(KK + 255) / 256, 256>>>(weight);
    vq_argmin_kernel<<<NVEC / BLK_V, 256, SMEM_BYTES>>>(inputs, weight);

    int gthreads = BB * DD * (TT / 4);
    vq_gather_kernel<<<(gthreads + 255) / 256, 256>>>(weight, out);

    if (out_size >= QOUT + NVEC) {
        vq_idx_kernel<<<(NVEC + 255) / 256, 256>>>(out + QOUT);
    }
}